// round 9
// baseline (speedup 1.0000x reference)
#include <cuda_runtime.h>
#include <cuda_fp16.h>
#include <math.h>
#include <stdint.h>

#define BATCH   4096
#define IN_DIM  1024
#define OUT_DIM 1024
#define DPC     16
#define N_DEND  16384

#define TILE_M  128
#define TILE_N  64
#define BK      64            // fp16 k per stage chunk (128B rows)
#define NCHUNK  48            // 3 passes * 1024 / 64
#define THREADS 256
#define STAGES  3
#define STAGE_SZ 24576        // A 16KB + B 8KB
#define B_OFF    16384
#define SMEM_BYTES (STAGES * STAGE_SZ)   // 73728 = 9*8KB -> 3 CTAs/SM
#define WSCALE  1024.0f
#define TAU     0.01f
#define FLAG_CAP 65536

// ---------------- static device scratch ----------------
__device__ __align__(256) __half g_xh[BATCH * IN_DIM];
__device__ __align__(256) __half g_xl[BATCH * IN_DIM];
__device__ __align__(256) __half g_wh[(size_t)N_DEND * IN_DIM];
__device__ __align__(256) __half g_wl[(size_t)N_DEND * IN_DIM];
__device__ float g_boost[N_DEND];
__device__ float g_b1s[N_DEND];
__device__ int   g_flags[FLAG_CAP];
__device__ int   g_nflag;

// ---------------- PTX helpers (portable to compute_103) ----------------
__device__ __forceinline__ uint32_t smem_u32(const void* p) {
    uint32_t a;
    asm("{ .reg .u64 t; cvta.to.shared.u64 t, %1; cvt.u32.u64 %0, t; }" : "=r"(a) : "l"(p));
    return a;
}
__device__ __forceinline__ void cp16(uint32_t dst, const void* src) {
    asm volatile("cp.async.cg.shared.global [%0], [%1], 16;" :: "r"(dst), "l"(src) : "memory");
}
#define CP_COMMIT() asm volatile("cp.async.commit_group;" ::: "memory")

#define LDSM4(r, addr) \
    asm volatile("ldmatrix.sync.aligned.m8n8.x4.shared.b16 {%0,%1,%2,%3}, [%4];" \
                 : "=r"((r)[0]), "=r"((r)[1]), "=r"((r)[2]), "=r"((r)[3]) : "r"(addr))

__device__ __forceinline__ void mma16816(float* c, const uint32_t* a,
                                         uint32_t b0, uint32_t b1) {
    asm volatile(
        "mma.sync.aligned.m16n8k16.row.col.f32.f16.f16.f32 "
        "{%0,%1,%2,%3}, {%4,%5,%6,%7}, {%8,%9}, {%0,%1,%2,%3};"
        : "+f"(c[0]), "+f"(c[1]), "+f"(c[2]), "+f"(c[3])
        : "r"(a[0]), "r"(a[1]), "r"(a[2]), "r"(a[3]), "r"(b0), "r"(b1));
}

// ---------------- prep kernels ----------------
__global__ void prep_misc_kernel(const float* __restrict__ duty, const float* __restrict__ b1) {
    int i = blockIdx.x * blockDim.x + threadIdx.x;
    if (i < N_DEND) {
        g_boost[i] = expf((1.0f / DPC - duty[i]) * 2.0f);
        g_b1s[i]   = b1[i] * WSCALE;
    }
    if (i == 0) g_nflag = 0;
}
__global__ void split_x_kernel(const float* __restrict__ x) {
    int i = blockIdx.x * blockDim.x + threadIdx.x;
    if (i < BATCH * IN_DIM) {
        float v = x[i];
        __half h = __float2half_rn(v);
        g_xh[i] = h;
        g_xl[i] = __float2half_rn(v - __half2float(h));
    }
}
__global__ void split_w_kernel(const float* __restrict__ w1) {
    size_t i = (size_t)blockIdx.x * blockDim.x + threadIdx.x;
    if (i < (size_t)N_DEND * IN_DIM) {
        float v = w1[i] * WSCALE;
        __half h = __float2half_rn(v);
        g_wh[i] = h;
        g_wl[i] = __float2half_rn(v - __half2float(h));
    }
}

// ---------------- stage loader ----------------
__device__ __forceinline__ void load_chunk(int t, int tid, uint32_t sb, int m0, int n0) {
    const int pass = t >> 4;                  // 0: xh*wh, 1: xh*wl, 2: xl*wh
    const int kc   = (t & 15) * BK;
    const __half* Ab = (pass == 2) ? g_xl : g_xh;
    const __half* Bb = (pass == 1) ? g_wl : g_wh;
    const uint32_t sA = sb + (uint32_t)(t % STAGES) * STAGE_SZ;
    const uint32_t sB = sA + B_OFF;
#pragma unroll
    for (int i = 0; i < 4; ++i) {             // A: 128 rows x 8 chunks of 16B
        int e = tid + i * THREADS;
        int r = e >> 3, c = e & 7;
        cp16(sA + r * 128 + ((c ^ (r & 7)) << 4),
             Ab + (size_t)(m0 + r) * IN_DIM + kc + c * 8);
    }
#pragma unroll
    for (int i = 0; i < 2; ++i) {             // B: 64 rows x 8 chunks
        int e = tid + i * THREADS;
        int r = e >> 3, c = e & 7;
        cp16(sB + r * 128 + ((c ^ (r & 7)) << 4),
             Bb + (size_t)(n0 + r) * IN_DIM + kc + c * 8);
    }
    CP_COMMIT();
}

// ---------------- main fused GEMM + WTA epilogue ----------------
__global__ __launch_bounds__(THREADS, 3)
void gemm_kernel(const float* __restrict__ w2, const float* __restrict__ b2,
                 float* __restrict__ out) {
    extern __shared__ char smem[];
    const uint32_t sb = smem_u32(smem);
    const int tid  = threadIdx.x;
    const int wid  = tid >> 5, lane = tid & 31;
    const int wm   = wid & 3;              // warp m index (32-row block)
    const int wn   = wid >> 2;             // warp n index (32-col block)
    const int ntile = blockIdx.x, btile = blockIdx.y;
    const int m0 = btile * TILE_M, n0 = ntile * TILE_N;

    const int h    = lane >> 4;                        // k-half selector
    const int lr   = lane & 15;
    const uint32_t aOff = (uint32_t)(wm * 32 + lr) * 128;
    const uint32_t bOff = (uint32_t)(wn * 32 + lr) * 128 + B_OFF;
    uint32_t swz[4];
#pragma unroll
    for (int ks = 0; ks < 4; ++ks)
        swz[ks] = (uint32_t)(((ks * 2 + h) ^ (lr & 7)) << 4);

    float c[2][4][4];
#pragma unroll
    for (int i = 0; i < 2; ++i)
#pragma unroll
        for (int j = 0; j < 4; ++j)
#pragma unroll
            for (int k = 0; k < 4; ++k) c[i][j][k] = 0.0f;

    load_chunk(0, tid, sb, m0, n0);
    load_chunk(1, tid, sb, m0, n0);

    uint32_t af[2][8], bf[2][8];

#pragma unroll 1
    for (int t = 0; t < NCHUNK; ++t) {
        if (t < NCHUNK - 1) asm volatile("cp.async.wait_group 1;" ::: "memory");
        else                asm volatile("cp.async.wait_group 0;" ::: "memory");
        __syncthreads();

        if (t + 2 < NCHUNK) load_chunk(t + 2, tid, sb, m0, n0);

        const uint32_t sS = sb + (uint32_t)(t % STAGES) * STAGE_SZ;
        // prime ks=0 fragments
        LDSM4(&af[0][0], sS + aOff + swz[0]);
        LDSM4(&af[0][4], sS + aOff + 2048 + swz[0]);
        LDSM4(&bf[0][0], sS + bOff + swz[0]);
        LDSM4(&bf[0][4], sS + bOff + 2048 + swz[0]);

#pragma unroll
        for (int ks = 0; ks < 4; ++ks) {
            const int cb = ks & 1, nb = cb ^ 1;
            if (ks < 3) {   // prefetch next ks fragments behind MMAs
                LDSM4(&af[nb][0], sS + aOff + swz[ks + 1]);
                LDSM4(&af[nb][4], sS + aOff + 2048 + swz[ks + 1]);
                LDSM4(&bf[nb][0], sS + bOff + swz[ks + 1]);
                LDSM4(&bf[nb][4], sS + bOff + 2048 + swz[ks + 1]);
            }
#pragma unroll
            for (int mt = 0; mt < 2; ++mt)
#pragma unroll
                for (int nt = 0; nt < 4; ++nt)
                    mma16816(c[mt][nt], &af[cb][mt * 4],
                             bf[cb][(nt >> 1) * 4 + (nt & 1)],
                             bf[cb][(nt >> 1) * 4 + (nt & 1) + 2]);
        }
    }

    // ---- shuffle-based boosted winner-take-all + output ----
    // c[mt][nt][rh*2+b] at row wm*32+mt*16+rh*8+(lane>>2), col wn*32+nt*8+(lane&3)*2+b
    const int g = lane >> 2, q = lane & 3;
#pragma unroll
    for (int mt = 0; mt < 2; ++mt) {
#pragma unroll
        for (int rh = 0; rh < 2; ++rh) {
            const int m = m0 + wm * 32 + mt * 16 + rh * 8 + g;
#pragma unroll
            for (int cc = 0; cc < 2; ++cc) {
                float bmax = -INFINITY, bsec = -INFINITY, dja = 0.0f;
                int ja = 0;
#pragma unroll
                for (int ntb = 0; ntb < 2; ++ntb) {
#pragma unroll
                    for (int b = 0; b < 2; ++b) {
                        const int j    = ntb * 8 + q * 2 + b;       // ascending j
                        const int colt = n0 + wn * 32 + cc * 16 + j;
                        float d  = c[mt][2 * cc + ntb][rh * 2 + b] + g_b1s[colt];
                        float bb = d * g_boost[colt];
                        if (bb > bmax) { bsec = bmax; bmax = bb; ja = j; dja = d; }
                        else if (bb > bsec) { bsec = bb; }
                    }
                }
#pragma unroll
                for (int off = 1; off <= 2; off <<= 1) {
                    float obmax = __shfl_xor_sync(0xffffffffu, bmax, off);
                    float obsec = __shfl_xor_sync(0xffffffffu, bsec, off);
                    float od    = __shfl_xor_sync(0xffffffffu, dja,  off);
                    int   oj    = __shfl_xor_sync(0xffffffffu, ja,   off);
                    if (obmax > bmax || (obmax == bmax && oj < ja)) {
                        bsec = fmaxf(bmax, obsec);
                        bmax = obmax; dja = od; ja = oj;
                    } else {
                        bsec = fmaxf(bsec, obmax);
                    }
                }
                if (q == 0) {
                    const int o = ntile * (TILE_N / DPC) + wn * 2 + cc;
                    out[(size_t)m * OUT_DIM + o] =
                        (dja * (1.0f / WSCALE)) * w2[o * DPC + ja] + b2[o];
                    if (bmax - bsec < TAU) {
                        int idx = atomicAdd(&g_nflag, 1);
                        if (idx < FLAG_CAP) g_flags[idx] = (m << 10) | o;
                    }
                }
            }
        }
    }
}

// ---------------- bit-exact fixup for near-tie cells ----------------
__global__ void fixup_kernel(const float* __restrict__ x,  const float* __restrict__ w1,
                             const float* __restrict__ b1, const float* __restrict__ w2,
                             const float* __restrict__ b2, float* __restrict__ out) {
    int n = g_nflag;
    if (n > FLAG_CAP) n = FLAG_CAP;
    const int gtid = blockIdx.x * blockDim.x + threadIdx.x;
    const int grp  = gtid >> 4;
    const int j    = gtid & 15;
    const int ngrp = (gridDim.x * blockDim.x) >> 4;
    for (int i = grp; i < n; i += ngrp) {
        const int f = g_flags[i];
        const int m = f >> 10, o = f & (OUT_DIM - 1);
        const float* xr = x  + (size_t)m * IN_DIM;
        const float* wr = w1 + (size_t)(o * DPC + j) * IN_DIM;
        float s = 0.0f;
#pragma unroll 8
        for (int k = 0; k < IN_DIM; ++k) s = fmaf(xr[k], wr[k], s);  // order preserved
        float d  = s + b1[o * DPC + j];
        float bb = d * g_boost[o * DPC + j];
        float bbb = bb, bd = d;
        int   bj  = j;
#pragma unroll
        for (int off = 8; off; off >>= 1) {
            float obb = __shfl_xor_sync(0xffffffffu, bbb, off);
            float od  = __shfl_xor_sync(0xffffffffu, bd,  off);
            int   oj  = __shfl_xor_sync(0xffffffffu, bj,  off);
            if (obb > bbb || (obb == bbb && oj < bj)) { bbb = obb; bd = od; bj = oj; }
        }
        if (j == 0) out[(size_t)m * OUT_DIM + o] = fmaf(bd, w2[o * DPC + bj], b2[o]);
    }
}

extern "C" void kernel_launch(void* const* d_in, const int* in_sizes, int n_in,
                              void* d_out, int out_size) {
    const float* x    = (const float*)d_in[0];
    const float* w1   = (const float*)d_in[1];
    const float* b1   = (const float*)d_in[2];
    const float* duty = (const float*)d_in[3];
    const float* w2   = (const float*)d_in[4];
    const float* b2   = (const float*)d_in[5];
    float* out = (float*)d_out;

    cudaFuncSetAttribute(gemm_kernel, cudaFuncAttributeMaxDynamicSharedMemorySize,
                         SMEM_BYTES);

    prep_misc_kernel<<<N_DEND / 256, 256>>>(duty, b1);
    split_x_kernel<<<(BATCH * IN_DIM) / 256, 256>>>(x);
    split_w_kernel<<<N_DEND * (IN_DIM / 256), 256>>>(w1);

    dim3 grid(N_DEND / TILE_N, BATCH / TILE_M);
    gemm_kernel<<<grid, THREADS, SMEM_BYTES>>>(w2, b2, out);
    fixup_kernel<<<512, 256>>>(x, w1, b1, w2, b2, out);
}

// round 10
// speedup vs baseline: 1.6673x; 1.6673x over previous
#include <cuda_runtime.h>
#include <cuda_fp16.h>
#include <math.h>
#include <stdint.h>

#define BATCH   4096
#define IN_DIM  1024
#define OUT_DIM 1024
#define DPC     16
#define N_DEND  16384

#define TILE_M  128
#define TILE_N  128
#define BK      64            // fp16 k per stage chunk (128B rows)
#define NCHUNK  48            // 3 passes * 1024 / 64
#define THREADS 256
#define STAGES  3
#define STAGE_SZ 32768        // A 16KB + B 16KB
#define B_OFF    16384
#define SMEM_BYTES (STAGES * STAGE_SZ + 128)   // +slot for next-tile id
#define NTILES_N (N_DEND / TILE_N)             // 128
#define NTILES   ((BATCH / TILE_M) * NTILES_N) // 4096
#define NCTA     296
#define WSCALE  1024.0f
#define TAU     0.01f
#define FLAG_CAP 65536

// ---------------- static device scratch ----------------
__device__ __align__(256) __half g_xh[BATCH * IN_DIM];
__device__ __align__(256) __half g_xl[BATCH * IN_DIM];
__device__ __align__(256) __half g_wh[(size_t)N_DEND * IN_DIM];
__device__ __align__(256) __half g_wl[(size_t)N_DEND * IN_DIM];
__device__ float g_boost[N_DEND];
__device__ float g_b1s[N_DEND];
__device__ int   g_flags[FLAG_CAP];
__device__ int   g_nflag;
__device__ int   g_tile_ctr;

// ---------------- PTX helpers (portable to compute_103) ----------------
__device__ __forceinline__ uint32_t smem_u32(const void* p) {
    uint32_t a;
    asm("{ .reg .u64 t; cvta.to.shared.u64 t, %1; cvt.u32.u64 %0, t; }" : "=r"(a) : "l"(p));
    return a;
}
__device__ __forceinline__ void cp16(uint32_t dst, const void* src) {
    asm volatile("cp.async.cg.shared.global [%0], [%1], 16;" :: "r"(dst), "l"(src) : "memory");
}
#define CP_COMMIT() asm volatile("cp.async.commit_group;" ::: "memory")

#define LDSM4(r, addr) \
    asm volatile("ldmatrix.sync.aligned.m8n8.x4.shared.b16 {%0,%1,%2,%3}, [%4];" \
                 : "=r"((r)[0]), "=r"((r)[1]), "=r"((r)[2]), "=r"((r)[3]) : "r"(addr))

__device__ __forceinline__ void mma16816(float* c, const uint32_t* a,
                                         uint32_t b0, uint32_t b1) {
    asm volatile(
        "mma.sync.aligned.m16n8k16.row.col.f32.f16.f16.f32 "
        "{%0,%1,%2,%3}, {%4,%5,%6,%7}, {%8,%9}, {%0,%1,%2,%3};"
        : "+f"(c[0]), "+f"(c[1]), "+f"(c[2]), "+f"(c[3])
        : "r"(a[0]), "r"(a[1]), "r"(a[2]), "r"(a[3]), "r"(b0), "r"(b1));
}

// ---------------- merged, vectorized prep ----------------
#define WBLOCKS 8192   // 16.7M w elems / 2048 per block
#define XBLOCKS 2048   // 4.19M x elems / 2048 per block
#define BBLOCKS (N_DEND / 256)
__device__ __forceinline__ void split8(const float* __restrict__ src,
                                       __half* __restrict__ dh,
                                       __half* __restrict__ dl,
                                       size_t base, float scale) {
    float4 v0 = *(const float4*)(src + base);
    float4 v1 = *(const float4*)(src + base + 4);
    float f[8] = {v0.x, v0.y, v0.z, v0.w, v1.x, v1.y, v1.z, v1.w};
    __half hh[8], ll[8];
#pragma unroll
    for (int i = 0; i < 8; ++i) {
        float s = f[i] * scale;
        hh[i] = __float2half_rn(s);
        ll[i] = __float2half_rn(s - __half2float(hh[i]));
    }
    *(uint4*)&dh[base] = *(uint4*)hh;
    *(uint4*)&dl[base] = *(uint4*)ll;
}
__global__ void prep_all(const float* __restrict__ x, const float* __restrict__ w1,
                         const float* __restrict__ duty, const float* __restrict__ b1) {
    const int b = blockIdx.x;
    if (b < WBLOCKS) {
        split8(w1, g_wh, g_wl, ((size_t)b * 256 + threadIdx.x) * 8, WSCALE);
    } else if (b < WBLOCKS + XBLOCKS) {
        split8(x, g_xh, g_xl, ((size_t)(b - WBLOCKS) * 256 + threadIdx.x) * 8, 1.0f);
    } else {
        int i = (b - WBLOCKS - XBLOCKS) * 256 + threadIdx.x;
        if (i < N_DEND) {
            g_boost[i] = expf((1.0f / DPC - duty[i]) * 2.0f);
            g_b1s[i]   = b1[i] * WSCALE;
        }
        if (i == 0) { g_nflag = 0; g_tile_ctr = NCTA; }
    }
}

// ---------------- stage loader ----------------
__device__ __forceinline__ void load_chunk(int t, int stage, int tid, uint32_t sb,
                                           int m0, int n0) {
    const int pass = t >> 4;                  // 0: xh*wh, 1: xh*wl, 2: xl*wh
    const int kc   = (t & 15) * BK;
    const __half* Ab = (pass == 2) ? g_xl : g_xh;
    const __half* Bb = (pass == 1) ? g_wl : g_wh;
    const uint32_t sA = sb + (uint32_t)stage * STAGE_SZ;
    const uint32_t sB = sA + B_OFF;
#pragma unroll
    for (int i = 0; i < 4; ++i) {             // A: 128 rows x 8 chunks of 16B
        int e = tid + i * THREADS;
        int r = e >> 3, c = e & 7;
        cp16(sA + r * 128 + ((c ^ (r & 7)) << 4),
             Ab + (size_t)(m0 + r) * IN_DIM + kc + c * 8);
    }
#pragma unroll
    for (int i = 0; i < 4; ++i) {             // B: 128 rows x 8 chunks
        int e = tid + i * THREADS;
        int r = e >> 3, c = e & 7;
        cp16(sB + r * 128 + ((c ^ (r & 7)) << 4),
             Bb + (size_t)(n0 + r) * IN_DIM + kc + c * 8);
    }
    CP_COMMIT();
}

// ---------------- persistent fused GEMM + WTA epilogue ----------------
__global__ __launch_bounds__(THREADS, 2)
void gemm_kernel(const float* __restrict__ w2, const float* __restrict__ b2,
                 float* __restrict__ out) {
    extern __shared__ char smem[];
    const uint32_t sb = smem_u32(smem);
    int* nts = (int*)(smem + STAGES * STAGE_SZ);
    const int tid  = threadIdx.x;
    const int wid  = tid >> 5, lane = tid & 31;
    const int wm   = wid & 1;              // warp m index (64-row block)
    const int wn   = wid >> 1;             // warp n index (32-col block)
    const int h    = lane >> 4;
    const int lr   = lane & 15;
    const uint32_t aOff = (uint32_t)(wm * 64 + lr) * 128;
    const uint32_t bOff = (uint32_t)(wn * 32 + lr) * 128 + B_OFF;
    uint32_t swz[4];
#pragma unroll
    for (int ks = 0; ks < 4; ++ks)
        swz[ks] = (uint32_t)(((ks * 2 + h) ^ (lr & 7)) << 4);

    float c[4][4][4];
#pragma unroll
    for (int i = 0; i < 4; ++i)
#pragma unroll
        for (int j = 0; j < 4; ++j)
#pragma unroll
            for (int k = 0; k < 4; ++k) c[i][j][k] = 0.0f;

    int cur = blockIdx.x;
    int curm0 = (cur >> 7) << 7, curn0 = (cur & 127) << 7;
    load_chunk(0, 0, tid, sb, curm0, curn0);
    load_chunk(1, 1, tid, sb, curm0, curn0);

    int stg = 0;
    const int g = lane >> 2, q = lane & 3;

    while (cur < NTILES) {
        int nxt = 0, nm0 = 0, nn0 = 0;
#pragma unroll 1
        for (int t = 0; t < NCHUNK; ++t) {
            if (t == NCHUNK - 1 && nxt >= NTILES)
                asm volatile("cp.async.wait_group 0;" ::: "memory");
            else
                asm volatile("cp.async.wait_group 1;" ::: "memory");
            __syncthreads();

            if (t == 40 && tid == 0) *nts = atomicAdd(&g_tile_ctr, 1);
            if (t == 46) {
                nxt = *(volatile int*)nts;
                nm0 = (nxt >> 7) << 7;
                nn0 = (nxt & 127) << 7;
            }
            {
                int lt   = t + 2;
                int lstg = stg + 2; if (lstg >= STAGES) lstg -= STAGES;
                if (lt < NCHUNK)        load_chunk(lt, lstg, tid, sb, curm0, curn0);
                else if (nxt < NTILES)  load_chunk(lt - NCHUNK, lstg, tid, sb, nm0, nn0);
            }

            const uint32_t sS = sb + (uint32_t)stg * STAGE_SZ;
#pragma unroll
            for (int ks = 0; ks < 4; ++ks) {
                uint32_t af[16], bf[8];
#pragma unroll
                for (int mt = 0; mt < 4; ++mt)
                    LDSM4(&af[mt * 4], sS + aOff + (uint32_t)mt * 2048 + swz[ks]);
#pragma unroll
                for (int nh = 0; nh < 2; ++nh)
                    LDSM4(&bf[nh * 4], sS + bOff + (uint32_t)nh * 2048 + swz[ks]);
#pragma unroll
                for (int mt = 0; mt < 4; ++mt)
#pragma unroll
                    for (int nt = 0; nt < 4; ++nt)
                        mma16816(c[mt][nt], &af[mt * 4],
                                 bf[(nt >> 1) * 4 + (nt & 1)],
                                 bf[(nt >> 1) * 4 + (nt & 1) + 2]);
            }
            ++stg; if (stg == STAGES) stg = 0;
        }

        // ---- epilogue for tile `cur` (loads for `nxt` already in flight) ----
#pragma unroll
        for (int mt = 0; mt < 4; ++mt) {
#pragma unroll
            for (int rh = 0; rh < 2; ++rh) {
                const int m = curm0 + wm * 64 + mt * 16 + rh * 8 + g;
#pragma unroll
                for (int cc = 0; cc < 2; ++cc) {
                    float bmax = -INFINITY, bsec = -INFINITY, dja = 0.0f;
                    int ja = 0;
#pragma unroll
                    for (int ntb = 0; ntb < 2; ++ntb) {
#pragma unroll
                        for (int b = 0; b < 2; ++b) {
                            const int j    = ntb * 8 + q * 2 + b;   // ascending j
                            const int colt = curn0 + wn * 32 + cc * 16 + j;
                            float d  = c[mt][2 * cc + ntb][rh * 2 + b] + g_b1s[colt];
                            float bb = d * g_boost[colt];
                            if (bb > bmax) { bsec = bmax; bmax = bb; ja = j; dja = d; }
                            else if (bb > bsec) { bsec = bb; }
                        }
                    }
#pragma unroll
                    for (int off = 1; off <= 2; off <<= 1) {
                        float obmax = __shfl_xor_sync(0xffffffffu, bmax, off);
                        float obsec = __shfl_xor_sync(0xffffffffu, bsec, off);
                        float od    = __shfl_xor_sync(0xffffffffu, dja,  off);
                        int   oj    = __shfl_xor_sync(0xffffffffu, ja,   off);
                        if (obmax > bmax || (obmax == bmax && oj < ja)) {
                            bsec = fmaxf(bmax, obsec);
                            bmax = obmax; dja = od; ja = oj;
                        } else {
                            bsec = fmaxf(bsec, obmax);
                        }
                    }
                    if (q == 0) {
                        const int o = (curn0 >> 4) + wn * 2 + cc;
                        out[(size_t)m * OUT_DIM + o] =
                            (dja * (1.0f / WSCALE)) * w2[o * DPC + ja] + b2[o];
                        if (bmax - bsec < TAU) {
                            int idx = atomicAdd(&g_nflag, 1);
                            if (idx < FLAG_CAP) g_flags[idx] = (m << 10) | o;
                        }
                    }
                }
            }
        }

#pragma unroll
        for (int i = 0; i < 4; ++i)
#pragma unroll
            for (int j = 0; j < 4; ++j)
#pragma unroll
                for (int k = 0; k < 4; ++k) c[i][j][k] = 0.0f;

        cur = nxt; curm0 = nm0; curn0 = nn0;
    }
}

// ---------------- bit-exact fixup for near-tie cells ----------------
__global__ void fixup_kernel(const float* __restrict__ x,  const float* __restrict__ w1,
                             const float* __restrict__ b1, const float* __restrict__ w2,
                             const float* __restrict__ b2, float* __restrict__ out) {
    int n = g_nflag;
    if (n > FLAG_CAP) n = FLAG_CAP;
    const int gtid = blockIdx.x * blockDim.x + threadIdx.x;
    const int grp  = gtid >> 4;
    const int j    = gtid & 15;
    const int ngrp = (gridDim.x * blockDim.x) >> 4;
    for (int i = grp; i < n; i += ngrp) {
        const int f = g_flags[i];
        const int m = f >> 10, o = f & (OUT_DIM - 1);
        const float* xr = x  + (size_t)m * IN_DIM;
        const float* wr = w1 + (size_t)(o * DPC + j) * IN_DIM;
        float s = 0.0f;
#pragma unroll 8
        for (int k = 0; k < IN_DIM; ++k) s = fmaf(xr[k], wr[k], s);  // order preserved
        float d  = s + b1[o * DPC + j];
        float bb = d * g_boost[o * DPC + j];
        float bbb = bb, bd = d;
        int   bj  = j;
#pragma unroll
        for (int off = 8; off; off >>= 1) {
            float obb = __shfl_xor_sync(0xffffffffu, bbb, off);
            float od  = __shfl_xor_sync(0xffffffffu, bd,  off);
            int   oj  = __shfl_xor_sync(0xffffffffu, bj,  off);
            if (obb > bbb || (obb == bbb && oj < bj)) { bbb = obb; bd = od; bj = oj; }
        }
        if (j == 0) out[(size_t)m * OUT_DIM + o] = fmaf(bd, w2[o * DPC + bj], b2[o]);
    }
}

extern "C" void kernel_launch(void* const* d_in, const int* in_sizes, int n_in,
                              void* d_out, int out_size) {
    const float* x    = (const float*)d_in[0];
    const float* w1   = (const float*)d_in[1];
    const float* b1   = (const float*)d_in[2];
    const float* duty = (const float*)d_in[3];
    const float* w2   = (const float*)d_in[4];
    const float* b2   = (const float*)d_in[5];
    float* out = (float*)d_out;

    cudaFuncSetAttribute(gemm_kernel, cudaFuncAttributeMaxDynamicSharedMemorySize,
                         SMEM_BYTES);

    prep_all<<<WBLOCKS + XBLOCKS + BBLOCKS, 256>>>(x, w1, duty, b1);
    gemm_kernel<<<NCTA, THREADS, SMEM_BYTES>>>(w2, b2, out);
    fixup_kernel<<<512, 256>>>(x, w1, b1, w2, b2, out);
}

// round 13
// speedup vs baseline: 2.6093x; 1.5650x over previous
#include <cuda_runtime.h>
#include <cuda_fp16.h>
#include <math.h>
#include <stdint.h>

#define BATCH   4096
#define IN_DIM  1024
#define OUT_DIM 1024
#define DPC     16
#define N_DEND  16384

#define TILE_M  128
#define TILE_N  128
#define BK      64            // fp16 k per stage chunk (128B rows)
#define NCHUNK  16            // single pass: 1024 / 64
#define THREADS 256
#define STAGES  3
#define STAGE_SZ 32768        // A 16KB + B 16KB
#define B_OFF    16384
#define SMEM_BYTES (STAGES * STAGE_SZ + 128)
#define NTILES   ((BATCH / TILE_M) * (N_DEND / TILE_N))  // 4096
#define NCTA     296
#define WSCALE  1024.0f
#define TAU_S   2.0f          // flag threshold, scaled units (~7 sigma of pair error)
#define FLAG_CAP 262144

// ---------------- static device scratch ----------------
__device__ __align__(256) __half g_xh[BATCH * IN_DIM];
__device__ __align__(256) __half g_wh[(size_t)N_DEND * IN_DIM];
__device__ float g_boost[N_DEND];
__device__ float g_b1s[N_DEND];
__device__ int   g_flagc[FLAG_CAP];
__device__ int   g_flagm[FLAG_CAP];
__device__ int   g_nflag;
__device__ int   g_tile_ctr;

// ---------------- PTX helpers (portable to compute_103) ----------------
__device__ __forceinline__ uint32_t smem_u32(const void* p) {
    uint32_t a;
    asm("{ .reg .u64 t; cvta.to.shared.u64 t, %1; cvt.u32.u64 %0, t; }" : "=r"(a) : "l"(p));
    return a;
}
__device__ __forceinline__ void cp16(uint32_t dst, const void* src) {
    asm volatile("cp.async.cg.shared.global [%0], [%1], 16;" :: "r"(dst), "l"(src) : "memory");
}
#define CP_COMMIT() asm volatile("cp.async.commit_group;" ::: "memory")

#define LDSM4(r, addr) \
    asm volatile("ldmatrix.sync.aligned.m8n8.x4.shared.b16 {%0,%1,%2,%3}, [%4];" \
                 : "=r"((r)[0]), "=r"((r)[1]), "=r"((r)[2]), "=r"((r)[3]) : "r"(addr))

__device__ __forceinline__ void mma16816(float* c, const uint32_t* a,
                                         uint32_t b0, uint32_t b1) {
    asm volatile(
        "mma.sync.aligned.m16n8k16.row.col.f32.f16.f16.f32 "
        "{%0,%1,%2,%3}, {%4,%5,%6,%7}, {%8,%9}, {%0,%1,%2,%3};"
        : "+f"(c[0]), "+f"(c[1]), "+f"(c[2]), "+f"(c[3])
        : "r"(a[0]), "r"(a[1]), "r"(a[2]), "r"(a[3]), "r"(b0), "r"(b1));
}

// ---------------- merged, vectorized prep ----------------
#define WBLOCKS 8192   // 16.7M w elems / 2048 per block
#define XBLOCKS 2048   // 4.19M x elems / 2048 per block
#define BBLOCKS (N_DEND / 256)
__device__ __forceinline__ void conv8(const float* __restrict__ src,
                                      __half* __restrict__ dh,
                                      size_t base, float scale) {
    float4 v0 = *(const float4*)(src + base);
    float4 v1 = *(const float4*)(src + base + 4);
    float f[8] = {v0.x, v0.y, v0.z, v0.w, v1.x, v1.y, v1.z, v1.w};
    __half hh[8];
#pragma unroll
    for (int i = 0; i < 8; ++i) hh[i] = __float2half_rn(f[i] * scale);
    *(uint4*)&dh[base] = *(uint4*)hh;
}
__global__ void prep_all(const float* __restrict__ x, const float* __restrict__ w1,
                         const float* __restrict__ duty, const float* __restrict__ b1) {
    const int b = blockIdx.x;
    if (b < WBLOCKS) {
        conv8(w1, g_wh, ((size_t)b * 256 + threadIdx.x) * 8, WSCALE);
    } else if (b < WBLOCKS + XBLOCKS) {
        conv8(x, g_xh, ((size_t)(b - WBLOCKS) * 256 + threadIdx.x) * 8, 1.0f);
    } else {
        int i = (b - WBLOCKS - XBLOCKS) * 256 + threadIdx.x;
        if (i < N_DEND) {
            g_boost[i] = expf((1.0f / DPC - duty[i]) * 2.0f);
            g_b1s[i]   = b1[i] * WSCALE;
        }
        if (i == 0) { g_nflag = 0; g_tile_ctr = NCTA; }
    }
}

// ---------------- stage loader ----------------
__device__ __forceinline__ void load_chunk(int t, int stage, int tid, uint32_t sb,
                                           int m0, int n0) {
    const int kc = t * BK;
    const uint32_t sA = sb + (uint32_t)stage * STAGE_SZ;
    const uint32_t sB = sA + B_OFF;
#pragma unroll
    for (int i = 0; i < 4; ++i) {             // A: 128 rows x 8 chunks of 16B
        int e = tid + i * THREADS;
        int r = e >> 3, c = e & 7;
        cp16(sA + r * 128 + ((c ^ (r & 7)) << 4),
             g_xh + (size_t)(m0 + r) * IN_DIM + kc + c * 8);
    }
#pragma unroll
    for (int i = 0; i < 4; ++i) {             // B: 128 rows x 8 chunks
        int e = tid + i * THREADS;
        int r = e >> 3, c = e & 7;
        cp16(sB + r * 128 + ((c ^ (r & 7)) << 4),
             g_wh + (size_t)(n0 + r) * IN_DIM + kc + c * 8);
    }
    CP_COMMIT();
}

// ---------------- persistent fused GEMM + WTA epilogue ----------------
__global__ __launch_bounds__(THREADS, 2)
void gemm_kernel(const float* __restrict__ w2, const float* __restrict__ b2,
                 float* __restrict__ out) {
    extern __shared__ char smem[];
    const uint32_t sb = smem_u32(smem);
    int* nts = (int*)(smem + STAGES * STAGE_SZ);
    const int tid  = threadIdx.x;
    const int wid  = tid >> 5, lane = tid & 31;
    const int wm   = wid & 1;              // warp m index (64-row block)
    const int wn   = wid >> 1;             // warp n index (32-col block)
    const int h    = lane >> 4;
    const int lr   = lane & 15;
    const uint32_t aOff = (uint32_t)(wm * 64 + lr) * 128;
    const uint32_t bOff = (uint32_t)(wn * 32 + lr) * 128 + B_OFF;
    uint32_t swz[4];
#pragma unroll
    for (int ks = 0; ks < 4; ++ks)
        swz[ks] = (uint32_t)(((ks * 2 + h) ^ (lr & 7)) << 4);

    float c[4][4][4];
#pragma unroll
    for (int i = 0; i < 4; ++i)
#pragma unroll
        for (int j = 0; j < 4; ++j)
#pragma unroll
            for (int k = 0; k < 4; ++k) c[i][j][k] = 0.0f;

    int cur = blockIdx.x;
    int curm0 = (cur >> 7) << 7, curn0 = (cur & 127) << 7;
    load_chunk(0, 0, tid, sb, curm0, curn0);
    load_chunk(1, 1, tid, sb, curm0, curn0);

    int stg = 0;
    const int g = lane >> 2, q = lane & 3;

    while (cur < NTILES) {
        int nxt = 0, nm0 = 0, nn0 = 0;
#pragma unroll 1
        for (int t = 0; t < NCHUNK; ++t) {
            if (t == NCHUNK - 1 && nxt >= NTILES)
                asm volatile("cp.async.wait_group 0;" ::: "memory");
            else
                asm volatile("cp.async.wait_group 1;" ::: "memory");
            __syncthreads();

            if (t == NCHUNK - 8 && tid == 0) *nts = atomicAdd(&g_tile_ctr, 1);
            if (t == NCHUNK - 2) {
                nxt = *(volatile int*)nts;
                nm0 = (nxt >> 7) << 7;
                nn0 = (nxt & 127) << 7;
            }
            {
                int lt   = t + 2;
                int lstg = stg + 2; if (lstg >= STAGES) lstg -= STAGES;
                if (lt < NCHUNK)        load_chunk(lt, lstg, tid, sb, curm0, curn0);
                else if (nxt < NTILES)  load_chunk(lt - NCHUNK, lstg, tid, sb, nm0, nn0);
            }

            const uint32_t sS = sb + (uint32_t)stg * STAGE_SZ;
#pragma unroll
            for (int ks = 0; ks < 4; ++ks) {
                uint32_t af[16], bf[8];
#pragma unroll
                for (int mt = 0; mt < 4; ++mt)
                    LDSM4(&af[mt * 4], sS + aOff + (uint32_t)mt * 2048 + swz[ks]);
#pragma unroll
                for (int nh = 0; nh < 2; ++nh)
                    LDSM4(&bf[nh * 4], sS + bOff + (uint32_t)nh * 2048 + swz[ks]);
#pragma unroll
                for (int mt = 0; mt < 4; ++mt)
#pragma unroll
                    for (int nt = 0; nt < 4; ++nt)
                        mma16816(c[mt][nt], &af[mt * 4],
                                 bf[(nt >> 1) * 4 + (nt & 1)],
                                 bf[(nt >> 1) * 4 + (nt & 1) + 2]);
            }
            ++stg; if (stg == STAGES) stg = 0;
        }

        // ---- epilogue: boosted WTA with candidate-mask flagging ----
#pragma unroll
        for (int mt = 0; mt < 4; ++mt) {
#pragma unroll
            for (int rh = 0; rh < 2; ++rh) {
                const int m = curm0 + wm * 64 + mt * 16 + rh * 8 + g;
#pragma unroll
                for (int cc = 0; cc < 2; ++cc) {
                    float bbv[4];
                    float bmax = -INFINITY, dja = 0.0f;
                    int ja = 0;
#pragma unroll
                    for (int idx = 0; idx < 4; ++idx) {
                        const int ntb = idx >> 1, b = idx & 1;
                        const int j    = ntb * 8 + q * 2 + b;       // ascending j
                        const int colt = curn0 + wn * 32 + cc * 16 + j;
                        float d  = c[mt][2 * cc + ntb][rh * 2 + b] + g_b1s[colt];
                        float bb = d * g_boost[colt];
                        bbv[idx] = bb;
                        if (bb > bmax) { bmax = bb; ja = j; dja = d; }
                    }
#pragma unroll
                    for (int off = 1; off <= 2; off <<= 1) {
                        float obmax = __shfl_xor_sync(0xffffffffu, bmax, off);
                        float od    = __shfl_xor_sync(0xffffffffu, dja,  off);
                        int   oj    = __shfl_xor_sync(0xffffffffu, ja,   off);
                        if (obmax > bmax || (obmax == bmax && oj < ja)) {
                            bmax = obmax; dja = od; ja = oj;
                        }
                    }
                    // candidate mask: all j within TAU_S of the max
                    int mask = 0;
#pragma unroll
                    for (int idx = 0; idx < 4; ++idx) {
                        const int j = (idx >> 1) * 8 + q * 2 + (idx & 1);
                        if (bmax - bbv[idx] < TAU_S) mask |= (1 << j);
                    }
                    mask |= __shfl_xor_sync(0xffffffffu, mask, 1);
                    mask |= __shfl_xor_sync(0xffffffffu, mask, 2);
                    if (q == 0) {
                        const int o = (curn0 >> 4) + wn * 2 + cc;
                        out[(size_t)m * OUT_DIM + o] =
                            (dja * (1.0f / WSCALE)) * w2[o * DPC + ja] + b2[o];
                        if (__popc(mask) > 1) {
                            int idx = atomicAdd(&g_nflag, 1);
                            if (idx < FLAG_CAP) {
                                g_flagc[idx] = (m << 10) | o;
                                g_flagm[idx] = mask;
                            }
                        }
                    }
                }
            }
        }

#pragma unroll
        for (int i = 0; i < 4; ++i)
#pragma unroll
            for (int j = 0; j < 4; ++j)
#pragma unroll
                for (int k = 0; k < 4; ++k) c[i][j][k] = 0.0f;

        cur = nxt; curm0 = nm0; curn0 = nn0;
    }
}

// ---------------- bit-exact fixup for flagged cells ----------------
// Recompute exact (ascending-k fmaf) dendrite values for the candidates only,
// then first-index argmax across the 16-lane group.
__global__ void fixup_kernel(const float* __restrict__ x,  const float* __restrict__ w1,
                             const float* __restrict__ b1, const float* __restrict__ w2,
                             const float* __restrict__ b2, float* __restrict__ out) {
    int n = g_nflag;
    if (n > FLAG_CAP) n = FLAG_CAP;
    const int gtid = blockIdx.x * blockDim.x + threadIdx.x;
    const int grp  = gtid >> 4;
    const int j    = gtid & 15;
    const int ngrp = (gridDim.x * blockDim.x) >> 4;
    for (int i = grp; i < n; i += ngrp) {
        const int f    = g_flagc[i];
        const int mask = g_flagm[i];
        const int m = f >> 10, o = f & (OUT_DIM - 1);
        float bb = -INFINITY, d = 0.0f;
        if ((mask >> j) & 1) {
            const float* xr = x  + (size_t)m * IN_DIM;
            const float* wr = w1 + (size_t)(o * DPC + j) * IN_DIM;
            float s = 0.0f;
#pragma unroll 8
            for (int k = 0; k < IN_DIM; ++k) s = fmaf(xr[k], wr[k], s);  // order preserved
            d  = s + b1[o * DPC + j];
            bb = d * g_boost[o * DPC + j];
        }
        float bbb = bb, bd = d;
        int   bj  = j;
#pragma unroll
        for (int off = 8; off; off >>= 1) {
            float obb = __shfl_xor_sync(0xffffffffu, bbb, off);
            float od  = __shfl_xor_sync(0xffffffffu, bd,  off);
            int   oj  = __shfl_xor_sync(0xffffffffu, bj,  off);
            if (obb > bbb || (obb == bbb && oj < bj)) { bbb = obb; bd = od; bj = oj; }
        }
        if (j == 0) out[(size_t)m * OUT_DIM + o] = fmaf(bd, w2[o * DPC + bj], b2[o]);
    }
}

extern "C" void kernel_launch(void* const* d_in, const int* in_sizes, int n_in,
                              void* d_out, int out_size) {
    const float* x    = (const float*)d_in[0];
    const float* w1   = (const float*)d_in[1];
    const float* b1   = (const float*)d_in[2];
    const float* duty = (const float*)d_in[3];
    const float* w2   = (const float*)d_in[4];
    const float* b2   = (const float*)d_in[5];
    float* out = (float*)d_out;

    cudaFuncSetAttribute(gemm_kernel, cudaFuncAttributeMaxDynamicSharedMemorySize,
                         SMEM_BYTES);

    prep_all<<<WBLOCKS + XBLOCKS + BBLOCKS, 256>>>(x, w1, duty, b1);
    gemm_kernel<<<NCTA, THREADS, SMEM_BYTES>>>(w2, b2, out);
    fixup_kernel<<<1024, 256>>>(x, w1, b1, w2, b2, out);
}

// round 14
// speedup vs baseline: 3.5949x; 1.3777x over previous
#include <cuda_runtime.h>
#include <cuda_fp16.h>
#include <math.h>
#include <stdint.h>

#define BATCH   4096
#define IN_DIM  1024
#define OUT_DIM 1024
#define DPC     16
#define N_DEND  16384

#define TILE_M  128
#define TILE_N  128
#define BK      64            // fp16 k per stage chunk (128B rows)
#define NCHUNK  16            // single pass: 1024 / 64
#define THREADS 256
#define STAGES  3
#define STAGE_SZ 32768        // A 16KB + B 16KB
#define B_OFF    16384
#define SMEM_BYTES (STAGES * STAGE_SZ + 128)
#define NTILES   ((BATCH / TILE_M) * (N_DEND / TILE_N))  // 4096
#define NCTA     296
#define WSCALE  1024.0f
#define TAU_S   2.0f          // flag threshold, scaled units (~7.7 sigma of pair error)
#define FLAG_CAP 262144

// ---------------- static device scratch ----------------
__device__ __align__(256) __half g_xh[BATCH * IN_DIM];
__device__ __align__(256) __half g_wh[(size_t)N_DEND * IN_DIM];
__device__ float g_boost[N_DEND];
__device__ float g_b1s[N_DEND];
__device__ int   g_flagc[FLAG_CAP];
__device__ int   g_flagm[FLAG_CAP];
__device__ int   g_nflag;
__device__ int   g_tile_ctr;

// ---------------- PTX helpers (portable to compute_103) ----------------
__device__ __forceinline__ uint32_t smem_u32(const void* p) {
    uint32_t a;
    asm("{ .reg .u64 t; cvta.to.shared.u64 t, %1; cvt.u32.u64 %0, t; }" : "=r"(a) : "l"(p));
    return a;
}
__device__ __forceinline__ void cp16(uint32_t dst, const void* src) {
    asm volatile("cp.async.cg.shared.global [%0], [%1], 16;" :: "r"(dst), "l"(src) : "memory");
}
#define CP_COMMIT() asm volatile("cp.async.commit_group;" ::: "memory")

#define LDSM4(r, addr) \
    asm volatile("ldmatrix.sync.aligned.m8n8.x4.shared.b16 {%0,%1,%2,%3}, [%4];" \
                 : "=r"((r)[0]), "=r"((r)[1]), "=r"((r)[2]), "=r"((r)[3]) : "r"(addr))

__device__ __forceinline__ void mma16816(float* c, const uint32_t* a,
                                         uint32_t b0, uint32_t b1) {
    asm volatile(
        "mma.sync.aligned.m16n8k16.row.col.f32.f16.f16.f32 "
        "{%0,%1,%2,%3}, {%4,%5,%6,%7}, {%8,%9}, {%0,%1,%2,%3};"
        : "+f"(c[0]), "+f"(c[1]), "+f"(c[2]), "+f"(c[3])
        : "r"(a[0]), "r"(a[1]), "r"(a[2]), "r"(a[3]), "r"(b0), "r"(b1));
}

// ---------------- merged, vectorized prep ----------------
#define WBLOCKS 8192   // 16.7M w elems / 2048 per block
#define XBLOCKS 2048   // 4.19M x elems / 2048 per block
#define BBLOCKS (N_DEND / 256)
__device__ __forceinline__ void conv8(const float* __restrict__ src,
                                      __half* __restrict__ dh,
                                      size_t base, float scale) {
    float4 v0 = *(const float4*)(src + base);
    float4 v1 = *(const float4*)(src + base + 4);
    float f[8] = {v0.x, v0.y, v0.z, v0.w, v1.x, v1.y, v1.z, v1.w};
    __half hh[8];
#pragma unroll
    for (int i = 0; i < 8; ++i) hh[i] = __float2half_rn(f[i] * scale);
    *(uint4*)&dh[base] = *(uint4*)hh;
}
__global__ void prep_all(const float* __restrict__ x, const float* __restrict__ w1,
                         const float* __restrict__ duty, const float* __restrict__ b1) {
    const int b = blockIdx.x;
    if (b < WBLOCKS) {
        conv8(w1, g_wh, ((size_t)b * 256 + threadIdx.x) * 8, WSCALE);
    } else if (b < WBLOCKS + XBLOCKS) {
        conv8(x, g_xh, ((size_t)(b - WBLOCKS) * 256 + threadIdx.x) * 8, 1.0f);
    } else {
        int i = (b - WBLOCKS - XBLOCKS) * 256 + threadIdx.x;
        if (i < N_DEND) {
            g_boost[i] = expf((1.0f / DPC - duty[i]) * 2.0f);
            g_b1s[i]   = b1[i] * WSCALE;
        }
        if (i == 0) { g_nflag = 0; g_tile_ctr = NCTA; }
    }
}

// ---------------- stage loader ----------------
__device__ __forceinline__ void load_chunk(int t, int stage, int tid, uint32_t sb,
                                           int m0, int n0) {
    const int kc = t * BK;
    const uint32_t sA = sb + (uint32_t)stage * STAGE_SZ;
    const uint32_t sB = sA + B_OFF;
#pragma unroll
    for (int i = 0; i < 4; ++i) {             // A: 128 rows x 8 chunks of 16B
        int e = tid + i * THREADS;
        int r = e >> 3, c = e & 7;
        cp16(sA + r * 128 + ((c ^ (r & 7)) << 4),
             g_xh + (size_t)(m0 + r) * IN_DIM + kc + c * 8);
    }
#pragma unroll
    for (int i = 0; i < 4; ++i) {             // B: 128 rows x 8 chunks
        int e = tid + i * THREADS;
        int r = e >> 3, c = e & 7;
        cp16(sB + r * 128 + ((c ^ (r & 7)) << 4),
             g_wh + (size_t)(n0 + r) * IN_DIM + kc + c * 8);
    }
    CP_COMMIT();
}

// ---------------- persistent fused GEMM + WTA epilogue ----------------
__global__ __launch_bounds__(THREADS, 2)
void gemm_kernel(const float* __restrict__ w2, const float* __restrict__ b2,
                 float* __restrict__ out) {
    extern __shared__ char smem[];
    const uint32_t sb = smem_u32(smem);
    int* nts = (int*)(smem + STAGES * STAGE_SZ);
    const int tid  = threadIdx.x;
    const int wid  = tid >> 5, lane = tid & 31;
    const int wm   = wid & 1;              // warp m index (64-row block)
    const int wn   = wid >> 1;             // warp n index (32-col block)
    const int h    = lane >> 4;
    const int lr   = lane & 15;
    const uint32_t aOff = (uint32_t)(wm * 64 + lr) * 128;
    const uint32_t bOff = (uint32_t)(wn * 32 + lr) * 128 + B_OFF;
    uint32_t swz[4];
#pragma unroll
    for (int ks = 0; ks < 4; ++ks)
        swz[ks] = (uint32_t)(((ks * 2 + h) ^ (lr & 7)) << 4);

    float c[4][4][4];
#pragma unroll
    for (int i = 0; i < 4; ++i)
#pragma unroll
        for (int j = 0; j < 4; ++j)
#pragma unroll
            for (int k = 0; k < 4; ++k) c[i][j][k] = 0.0f;

    int cur = blockIdx.x;
    int curm0 = (cur >> 7) << 7, curn0 = (cur & 127) << 7;
    load_chunk(0, 0, tid, sb, curm0, curn0);
    load_chunk(1, 1, tid, sb, curm0, curn0);

    int stg = 0;
    const int g = lane >> 2, q = lane & 3;

    while (cur < NTILES) {
        int nxt = 0, nm0 = 0, nn0 = 0;
#pragma unroll 1
        for (int t = 0; t < NCHUNK; ++t) {
            if (t == NCHUNK - 1 && nxt >= NTILES)
                asm volatile("cp.async.wait_group 0;" ::: "memory");
            else
                asm volatile("cp.async.wait_group 1;" ::: "memory");
            __syncthreads();

            if (t == NCHUNK - 8 && tid == 0) *nts = atomicAdd(&g_tile_ctr, 1);
            if (t == NCHUNK - 2) {
                nxt = *(volatile int*)nts;
                nm0 = (nxt >> 7) << 7;
                nn0 = (nxt & 127) << 7;
            }
            {
                int lt   = t + 2;
                int lstg = stg + 2; if (lstg >= STAGES) lstg -= STAGES;
                if (lt < NCHUNK)        load_chunk(lt, lstg, tid, sb, curm0, curn0);
                else if (nxt < NTILES)  load_chunk(lt - NCHUNK, lstg, tid, sb, nm0, nn0);
            }

            const uint32_t sS = sb + (uint32_t)stg * STAGE_SZ;
#pragma unroll
            for (int ks = 0; ks < 4; ++ks) {
                uint32_t af[16], bf[8];
#pragma unroll
                for (int mt = 0; mt < 4; ++mt)
                    LDSM4(&af[mt * 4], sS + aOff + (uint32_t)mt * 2048 + swz[ks]);
#pragma unroll
                for (int nh = 0; nh < 2; ++nh)
                    LDSM4(&bf[nh * 4], sS + bOff + (uint32_t)nh * 2048 + swz[ks]);
#pragma unroll
                for (int mt = 0; mt < 4; ++mt)
#pragma unroll
                    for (int nt = 0; nt < 4; ++nt)
                        mma16816(c[mt][nt], &af[mt * 4],
                                 bf[(nt >> 1) * 4 + (nt & 1)],
                                 bf[(nt >> 1) * 4 + (nt & 1) + 2]);
            }
            ++stg; if (stg == STAGES) stg = 0;
        }

        // ---- epilogue: boosted WTA with candidate-mask flagging ----
#pragma unroll
        for (int mt = 0; mt < 4; ++mt) {
#pragma unroll
            for (int rh = 0; rh < 2; ++rh) {
                const int m = curm0 + wm * 64 + mt * 16 + rh * 8 + g;
#pragma unroll
                for (int cc = 0; cc < 2; ++cc) {
                    float bbv[4];
                    float bmax = -INFINITY, dja = 0.0f;
                    int ja = 0;
#pragma unroll
                    for (int idx = 0; idx < 4; ++idx) {
                        const int ntb = idx >> 1, b = idx & 1;
                        const int j    = ntb * 8 + q * 2 + b;       // ascending j
                        const int colt = curn0 + wn * 32 + cc * 16 + j;
                        float d  = c[mt][2 * cc + ntb][rh * 2 + b] + g_b1s[colt];
                        float bb = d * g_boost[colt];
                        bbv[idx] = bb;
                        if (bb > bmax) { bmax = bb; ja = j; dja = d; }
                    }
#pragma unroll
                    for (int off = 1; off <= 2; off <<= 1) {
                        float obmax = __shfl_xor_sync(0xffffffffu, bmax, off);
                        float od    = __shfl_xor_sync(0xffffffffu, dja,  off);
                        int   oj    = __shfl_xor_sync(0xffffffffu, ja,   off);
                        if (obmax > bmax || (obmax == bmax && oj < ja)) {
                            bmax = obmax; dja = od; ja = oj;
                        }
                    }
                    // candidate mask: all j within TAU_S of the max
                    int mask = 0;
#pragma unroll
                    for (int idx = 0; idx < 4; ++idx) {
                        const int j = (idx >> 1) * 8 + q * 2 + (idx & 1);
                        if (bmax - bbv[idx] < TAU_S) mask |= (1 << j);
                    }
                    mask |= __shfl_xor_sync(0xffffffffu, mask, 1);
                    mask |= __shfl_xor_sync(0xffffffffu, mask, 2);
                    if (q == 0) {
                        const int o = (curn0 >> 4) + wn * 2 + cc;
                        out[(size_t)m * OUT_DIM + o] =
                            (dja * (1.0f / WSCALE)) * w2[o * DPC + ja] + b2[o];
                        if (__popc(mask) > 1) {
                            int idx = atomicAdd(&g_nflag, 1);
                            if (idx < FLAG_CAP) {
                                g_flagc[idx] = (m << 10) | o;
                                g_flagm[idx] = mask;
                            }
                        }
                    }
                }
            }
        }

#pragma unroll
        for (int i = 0; i < 4; ++i)
#pragma unroll
            for (int j = 0; j < 4; ++j)
#pragma unroll
                for (int k = 0; k < 4; ++k) c[i][j][k] = 0.0f;

        cur = nxt; curm0 = nm0; curn0 = nn0;
    }
}

// ---------------- bit-exact fixup for flagged cells ----------------
// Exact ascending-k fp32 fmaf chain per candidate dendrite, but with float4
// loads (same arithmetic order: accumulate .x,.y,.z,.w sequentially).
__global__ void fixup_kernel(const float* __restrict__ x,  const float* __restrict__ w1,
                             const float* __restrict__ b1, const float* __restrict__ w2,
                             const float* __restrict__ b2, float* __restrict__ out) {
    int n = g_nflag;
    if (n > FLAG_CAP) n = FLAG_CAP;
    const int gtid = blockIdx.x * blockDim.x + threadIdx.x;
    const int grp  = gtid >> 4;
    const int j    = gtid & 15;
    const int ngrp = (gridDim.x * blockDim.x) >> 4;
    for (int i = grp; i < n; i += ngrp) {
        const int f    = g_flagc[i];
        const int mask = g_flagm[i];
        const int m = f >> 10, o = f & (OUT_DIM - 1);
        float bb = -INFINITY, d = 0.0f;
        if ((mask >> j) & 1) {
            const float4* xr = (const float4*)(x  + (size_t)m * IN_DIM);
            const float4* wr = (const float4*)(w1 + (size_t)(o * DPC + j) * IN_DIM);
            float s = 0.0f;
#pragma unroll 4
            for (int k = 0; k < IN_DIM / 4; ++k) {
                float4 xv = __ldg(&xr[k]);
                float4 wv = __ldg(&wr[k]);
                s = fmaf(xv.x, wv.x, s);   // strict ascending-k order preserved
                s = fmaf(xv.y, wv.y, s);
                s = fmaf(xv.z, wv.z, s);
                s = fmaf(xv.w, wv.w, s);
            }
            d  = s + b1[o * DPC + j];
            bb = d * g_boost[o * DPC + j];
        }
        float bbb = bb, bd = d;
        int   bj  = j;
#pragma unroll
        for (int off = 8; off; off >>= 1) {
            float obb = __shfl_xor_sync(0xffffffffu, bbb, off);
            float od  = __shfl_xor_sync(0xffffffffu, bd,  off);
            int   oj  = __shfl_xor_sync(0xffffffffu, bj,  off);
            if (obb > bbb || (obb == bbb && oj < bj)) { bbb = obb; bd = od; bj = oj; }
        }
        if (j == 0) out[(size_t)m * OUT_DIM + o] = fmaf(bd, w2[o * DPC + bj], b2[o]);
    }
}

extern "C" void kernel_launch(void* const* d_in, const int* in_sizes, int n_in,
                              void* d_out, int out_size) {
    const float* x    = (const float*)d_in[0];
    const float* w1   = (const float*)d_in[1];
    const float* b1   = (const float*)d_in[2];
    const float* duty = (const float*)d_in[3];
    const float* w2   = (const float*)d_in[4];
    const float* b2   = (const float*)d_in[5];
    float* out = (float*)d_out;

    cudaFuncSetAttribute(gemm_kernel, cudaFuncAttributeMaxDynamicSharedMemorySize,
                         SMEM_BYTES);

    prep_all<<<WBLOCKS + XBLOCKS + BBLOCKS, 256>>>(x, w1, duty, b1);
    gemm_kernel<<<NCTA, THREADS, SMEM_BYTES>>>(w2, b2, out);
    fixup_kernel<<<2048, 256>>>(x, w1, b1, w2, b2, out);
}